// round 8
// baseline (speedup 1.0000x reference)
#include <cuda_runtime.h>
#include <math.h>
#include <stdint.h>

// Problem constants
#define BB 2
#define TT 2048
#define CC 1024
#define HH 16
#define HS 64
#define NROWS (BB*TT)        // 4096
#define LN_EPS 1e-5f

// ---------------------------------------------------------------------------
// Scratch
// ---------------------------------------------------------------------------
__device__ float g_h   [NROWS*CC];
__device__ float g_wqkv[CC*3*CC];      // PERMUTED qkv weight (k-pair frag order)
__device__ float g_bqkv[3*CC];
__device__ float g_qkv [NROWS*3*CC];
__device__ float g_attn[NROWS*CC];
__device__ float g_x1  [NROWS*CC];
__device__ float g_h2  [NROWS*CC];
__device__ float g_ff  [NROWS*4*CC];
__device__ float g_wor [CC*CC];        // permuted Wo
__device__ float g_w1r [CC*4*CC];      // permuted W1
__device__ float g_w2r [4*CC*CC];      // permuted W2

__device__ __forceinline__ float to_tf32(float x) {
    uint32_t u;
    asm("cvt.rna.tf32.f32 %0, %1;" : "=r"(u) : "f"(x));
    return __uint_as_float(u);
}
__device__ __forceinline__ float ex2_mufu(float y) {
    float r;
    asm("ex2.approx.ftz.f32 %0, %1;" : "=f"(r) : "f"(y));
    return r;
}
__device__ __forceinline__ float ex2_poly(float y) {
    float r = y + 12582912.f;
    int   n = __float_as_int(r);
    float t = r - 12582912.f;
    float f = y - t;
    float p = 0.00961813f;
    p = fmaf(p, f, 0.05550411f);
    p = fmaf(p, f, 0.24022651f);
    p = fmaf(p, f, 0.69314718f);
    p = fmaf(p, f, 1.0f);
    return __int_as_float(__float_as_int(p) + (n << 23));
}
__device__ __forceinline__ uint32_t pack_bf16x2(float lo, float hi) {
    uint32_t r;
    asm("cvt.rn.bf16x2.f32 %0, %1, %2;" : "=r"(r) : "f"(hi), "f"(lo));
    return r;
}
__device__ __forceinline__ void cp16(uint32_t dst, const void* src) {
    asm volatile("cp.async.cg.shared.global [%0], [%1], 16;\n"
                 :: "r"(dst), "l"(src));
}
#define CP_COMMIT() asm volatile("cp.async.commit_group;\n" ::: "memory")
#define CP_WAIT(n)  asm volatile("cp.async.wait_group %0;\n" :: "n"(n) : "memory")

// ---------------------------------------------------------------------------
// Weight permute: B[K,N] row-major -> fragment-pair layout.
// dst (as float2): [(k0/32)*N + n]*16 + q,  q = ks*4+tg,
//   value = (tf32(B[k0+8ks+tg][n]), tf32(B[k0+8ks+tg+4][n]))
// grid (N/64, K/32), block 256, smem tile 32x64 (stride 68: float4-safe)
// ---------------------------------------------------------------------------
__global__ void permute_w_kernel(const float* __restrict__ src,
                                 float* __restrict__ dst, int K, int N) {
    __shared__ float smw[32][68];     // stride 68 (mult of 4) -> aligned float4
    int n0 = blockIdx.x * 64, k0 = blockIdx.y * 32;
    int tid = threadIdx.x;
    int r = tid >> 3, c8 = (tid & 7) * 8;
    {
        float4 v0 = *(const float4*)&src[(size_t)(k0 + r)*N + n0 + c8];
        float4 v1 = *(const float4*)&src[(size_t)(k0 + r)*N + n0 + c8 + 4];
        *(float4*)&smw[r][c8]     = v0;
        *(float4*)&smw[r][c8 + 4] = v1;
    }
    __syncthreads();
    float2* d2 = (float2*)dst;
#pragma unroll
    for (int p = 0; p < 4; p++) {
        int idx = tid + p*256;          // 1024 = 64 n x 16 q
        int nl = idx >> 4, q = idx & 15;
        int ks = q >> 2, tg = q & 3;
        float2 v;
        v.x = to_tf32(smw[8*ks + tg    ][nl]);
        v.y = to_tf32(smw[8*ks + tg + 4][nl]);
        d2[((size_t)(k0 >> 5)*N + n0 + nl)*16 + q] = v;
    }
}

// ---------------------------------------------------------------------------
// QKV weight pack+permute: Wq/Wk/Wv [H,C,HS] -> g_wqkv fragment layout
// (B matrix [K=C, N=3C], n = w*1024 + h*64 + d).  grid (CC/32, HH), block 256
// ---------------------------------------------------------------------------
__global__ void pack_qkv_perm_kernel(const float* __restrict__ Wq,
                                     const float* __restrict__ Wk,
                                     const float* __restrict__ Wv) {
    __shared__ float smw[32][68];     // stride 68: aligned float4 stores
    int c0 = blockIdx.x * 32, h = blockIdx.y;
    int tid = threadIdx.x;
    int r = tid >> 3, c8 = (tid & 7) * 8;
    const float* srcs[3] = {Wq, Wk, Wv};
    float2* d2 = (float2*)g_wqkv;
    const int N = 3*CC;
#pragma unroll
    for (int m = 0; m < 3; m++) {
        const float* s = srcs[m] + ((size_t)h*CC + c0)*HS;
        {
            float4 v0 = *(const float4*)&s[(size_t)r*HS + c8];
            float4 v1 = *(const float4*)&s[(size_t)r*HS + c8 + 4];
            *(float4*)&smw[r][c8]     = v0;
            *(float4*)&smw[r][c8 + 4] = v1;
        }
        __syncthreads();
#pragma unroll
        for (int p = 0; p < 4; p++) {
            int idx = tid + p*256;
            int nl = idx >> 4, q = idx & 15;
            int ks = q >> 2, tg = q & 3;
            float2 v;
            v.x = to_tf32(smw[8*ks + tg    ][nl]);
            v.y = to_tf32(smw[8*ks + tg + 4][nl]);
            int n = m*CC + h*HS + nl;
            d2[((size_t)(c0 >> 5)*N + n)*16 + q] = v;
        }
        __syncthreads();
    }
}

__global__ void pack_bias_kernel(const float* __restrict__ bq,
                                 const float* __restrict__ bk,
                                 const float* __restrict__ bv) {
    int e = blockIdx.x * blockDim.x + threadIdx.x;
    if (e < CC) {
        g_bqkv[e]        = bq[e];
        g_bqkv[CC + e]   = bk[e];
        g_bqkv[2*CC + e] = bv[e];
    }
}

// ---------------------------------------------------------------------------
// LayerNorm over sequence axis (tf32-rounded output)
// ---------------------------------------------------------------------------
__global__ void __launch_bounds__(1024)
ln_seq_kernel(const float* __restrict__ x,
              const float* __restrict__ gamma,
              const float* __restrict__ beta,
              float* __restrict__ out) {
    int b  = blockIdx.y;
    int tx = threadIdx.x, ty = threadIdx.y;
    int c  = blockIdx.x * 32 + tx;
    const float* xp = x   + (size_t)b*TT*CC + c;
    float*       op = out + (size_t)b*TT*CC + c;

    float s = 0.f, sq = 0.f;
    for (int t = ty; t < TT; t += 32) {
        float v = xp[(size_t)t*CC];
        s += v; sq += v*v;
    }
    __shared__ float ssum[32][33];
    __shared__ float ssq [32][33];
    ssum[ty][tx] = s; ssq[ty][tx] = sq;
    __syncthreads();
    for (int off = 16; off > 0; off >>= 1) {
        if (ty < off) {
            ssum[ty][tx] += ssum[ty+off][tx];
            ssq [ty][tx] += ssq [ty+off][tx];
        }
        __syncthreads();
    }
    __shared__ float meanv[32], rstdv[32];
    if (ty == 0) {
        float mean = ssum[0][tx] * (1.0f / TT);
        float var  = (ssq[0][tx] - (float)TT * mean * mean) * (1.0f / (TT - 1));
        meanv[tx]  = mean;
        rstdv[tx]  = 1.0f / (sqrtf(var) + LN_EPS);
    }
    __syncthreads();
    float mean = meanv[tx], rstd = rstdv[tx];
    float g = gamma[c], bt = beta[c];
    for (int t = ty; t < TT; t += 32) {
        float v = xp[(size_t)t*CC];
        op[(size_t)t*CC] = to_tf32(g * ((v - mean) * rstd) + bt);
    }
}

// ---------------------------------------------------------------------------
// TF32 GEMM, 256x128 block tile, 8 warps (4m x 2n), warp tile 64x64.
// A row-major (pre-rounded tf32); B fragment-pair permuted layout.
// 2-stage cp.async double buffering.
// ---------------------------------------------------------------------------
#define MMA_TF32(d, a, b)                                                     \
    asm volatile(                                                             \
        "mma.sync.aligned.m16n8k8.row.col.f32.tf32.tf32.f32 "                 \
        "{%0,%1,%2,%3},{%4,%5,%6,%7},{%8,%9},{%0,%1,%2,%3};\n"                \
        : "+f"((d)[0]), "+f"((d)[1]), "+f"((d)[2]), "+f"((d)[3])              \
        : "r"((a)[0]), "r"((a)[1]), "r"((a)[2]), "r"((a)[3]),                 \
          "r"((b)[0]), "r"((b)[1]))

#define AS_FLOATS (256*36)   /* per buffer */
#define BS_FLOATS (128*36)   /* per buffer */
#define GEMM_SMEM ((2*AS_FLOATS + 2*BS_FLOATS)*4)

template<int DOBIAS, int DORELU, int DORES, int DOROUND>
__global__ void __launch_bounds__(256, 1)
gemm_tc_kernel(const float* __restrict__ A, const float* __restrict__ Bm,
               const float* __restrict__ bias, const float* __restrict__ res,
               float* __restrict__ Cm, int M, int N, int K) {
    extern __shared__ float smg[];
    int tid  = threadIdx.x;
    int lane = tid & 31, wid = tid >> 5;
    int wm = (wid >> 1) * 64;        // 4 m-warps
    int wn = (wid & 1) * 64;         // 2 n-warps
    int g  = lane >> 2;
    int tg = lane & 3;
    int m0 = blockIdx.y * 256, n0 = blockIdx.x * 128;

    float acc[4][8][4];
#pragma unroll
    for (int mf = 0; mf < 4; mf++)
#pragma unroll
        for (int nf = 0; nf < 8; nf++)
#pragma unroll
            for (int r = 0; r < 4; r++) acc[mf][nf][r] = 0.f;

    uint32_t smg_u = (uint32_t)__cvta_generic_to_shared(smg);
    int nk = K >> 5;

    int ar = tid >> 3, ac = (tid & 7) * 4;    // A: 8 passes of 32 rows

    // prologue: stage 0
    {
        uint32_t as_b = smg_u;
        uint32_t bs_b = smg_u + (2*AS_FLOATS)*4;
#pragma unroll
        for (int p = 0; p < 8; p++)
            cp16(as_b + ((ar + 32*p)*36 + ac)*4,
                 &A[(size_t)(m0 + ar + 32*p)*K + ac]);
        const float* bsrc = Bm + ((size_t)0*N + n0)*32;
#pragma unroll
        for (int p = 0; p < 4; p++) {
            int idx = tid + 256*p;
            int n = idx >> 3, j = idx & 7;
            cp16(bs_b + (n*36 + j*4)*4, bsrc + (size_t)n*32 + j*4);
        }
        CP_COMMIT();
    }

    for (int i = 0; i < nk; i++) {
        int buf = i & 1;
        if (i + 1 < nk) {
            int k0 = (i + 1) << 5;
            int nb = (i + 1) & 1;
            uint32_t as_b = smg_u + (nb*AS_FLOATS)*4;
            uint32_t bs_b = smg_u + (2*AS_FLOATS + nb*BS_FLOATS)*4;
#pragma unroll
            for (int p = 0; p < 8; p++)
                cp16(as_b + ((ar + 32*p)*36 + ac)*4,
                     &A[(size_t)(m0 + ar + 32*p)*K + k0 + ac]);
            const float* bsrc = Bm + ((size_t)(k0 >> 5)*N + n0)*32;
#pragma unroll
            for (int p = 0; p < 4; p++) {
                int idx = tid + 256*p;
                int n = idx >> 3, j = idx & 7;
                cp16(bs_b + (n*36 + j*4)*4, bsrc + (size_t)n*32 + j*4);
            }
            CP_COMMIT();
            CP_WAIT(1);
        } else {
            CP_WAIT(0);
        }
        __syncthreads();

        const float* As = smg + buf*AS_FLOATS;
        const float* Bs = smg + 2*AS_FLOATS + buf*BS_FLOATS;

#pragma unroll
        for (int ks = 0; ks < 4; ks++) {
            int kk = ks * 8;
            uint32_t afr[4][4];
#pragma unroll
            for (int mf = 0; mf < 4; mf++) {
                int r = wm + mf*16 + g;
                afr[mf][0] = __float_as_uint(As[(r    )*36 + kk + tg    ]);
                afr[mf][1] = __float_as_uint(As[(r + 8)*36 + kk + tg    ]);
                afr[mf][2] = __float_as_uint(As[(r    )*36 + kk + tg + 4]);
                afr[mf][3] = __float_as_uint(As[(r + 8)*36 + kk + tg + 4]);
            }
#pragma unroll
            for (int nf = 0; nf < 8; nf++) {
                int n = wn + nf*8 + g;
                float2 bp = *(const float2*)&Bs[n*36 + (ks*4 + tg)*2];
                uint32_t bfr[2];
                bfr[0] = __float_as_uint(bp.x);
                bfr[1] = __float_as_uint(bp.y);
#pragma unroll
                for (int mf = 0; mf < 4; mf++)
                    MMA_TF32(acc[mf][nf], afr[mf], bfr);
            }
        }
        __syncthreads();
    }

#pragma unroll
    for (int mf = 0; mf < 4; mf++) {
#pragma unroll
        for (int nf = 0; nf < 8; nf++) {
            int r  = m0 + wm + mf*16 + g;
            int cb = n0 + wn + nf*8 + 2*tg;
            float2 v0 = make_float2(acc[mf][nf][0], acc[mf][nf][1]);
            float2 v1 = make_float2(acc[mf][nf][2], acc[mf][nf][3]);
            if (DOBIAS) {
                float2 bsv = *(const float2*)&bias[cb];
                v0.x += bsv.x; v0.y += bsv.y;
                v1.x += bsv.x; v1.y += bsv.y;
            }
            if (DORELU) {
                v0.x = fmaxf(v0.x, 0.f); v0.y = fmaxf(v0.y, 0.f);
                v1.x = fmaxf(v1.x, 0.f); v1.y = fmaxf(v1.y, 0.f);
            }
            if (DORES) {
                float2 r0 = *(const float2*)&res[(size_t)r*N + cb];
                float2 r1 = *(const float2*)&res[(size_t)(r+8)*N + cb];
                v0.x += r0.x; v0.y += r0.y;
                v1.x += r1.x; v1.y += r1.y;
            }
            if (DOROUND) {
                v0.x = to_tf32(v0.x); v0.y = to_tf32(v0.y);
                v1.x = to_tf32(v1.x); v1.y = to_tf32(v1.y);
            }
            *(float2*)&Cm[(size_t)r*N + cb]     = v0;
            *(float2*)&Cm[(size_t)(r+8)*N + cb] = v1;
        }
    }
}

// ---------------------------------------------------------------------------
// bf16 tensor-core flash attention (verified R6)
// ---------------------------------------------------------------------------
#define QS32 36
#define KS32 36
#define VS32 36
#define SM32_QS 0
#define SM32_KS (128*QS32)
#define SM32_VT (SM32_KS + 64*KS32)
#define ATTN_SMEM ((SM32_VT + 64*VS32)*4)
#define QSCALE 0.18033688f

#define MMA_BF16(d, a, b)                                                     \
    asm volatile(                                                             \
        "mma.sync.aligned.m16n8k16.row.col.f32.bf16.bf16.f32 "                \
        "{%0,%1,%2,%3},{%4,%5,%6,%7},{%8,%9},{%0,%1,%2,%3};\n"                \
        : "+f"((d)[0]), "+f"((d)[1]), "+f"((d)[2]), "+f"((d)[3])              \
        : "r"((a)[0]), "r"((a)[1]), "r"((a)[2]), "r"((a)[3]),                 \
          "r"((b)[0]), "r"((b)[1]))

__global__ void __launch_bounds__(256, 2) attn_tc_kernel() {
    extern __shared__ uint32_t smu[];
    uint32_t* Qs = smu + SM32_QS;
    uint32_t* Ks = smu + SM32_KS;
    uint32_t* Vt = smu + SM32_VT;

    int tid = threadIdx.x, lane = tid & 31, wid = tid >> 5;
    int g = lane >> 2, tg = lane & 3;
    int b = blockIdx.z, h = blockIdx.y;
    int tq0 = blockIdx.x * 128;
    int wr = wid * 16;

    const float* qbase = g_qkv + (size_t)b*TT*3*CC + (size_t)h*HS;
    const float* kbase = qbase + CC;
    const float* vbase = qbase + 2*CC;

#pragma unroll
    for (int p = 0; p < 8; p++) {
        int idx = tid + p*256;
        int r = idx >> 4, c4 = idx & 15;
        float4 v = *(const float4*)&qbase[(size_t)(tq0 + r)*3*CC + c4*4];
        Qs[r*QS32 + c4*2    ] = pack_bf16x2(v.x*QSCALE, v.y*QSCALE);
        Qs[r*QS32 + c4*2 + 1] = pack_bf16x2(v.z*QSCALE, v.w*QSCALE);
    }

    float o[8][4];
#pragma unroll
    for (int i = 0; i < 8; i++)
#pragma unroll
        for (int j = 0; j < 4; j++) o[i][j] = 0.f;
    float lsum0 = 0.f, lsum1 = 0.f;

    __syncthreads();

    for (int kt = 0; kt < TT; kt += 64) {
#pragma unroll
        for (int p = 0; p < 4; p++) {
            int idx = tid + p*256;
            int r = idx >> 4, c4 = idx & 15;
            float4 v = *(const float4*)&kbase[(size_t)(kt + r)*3*CC + c4*4];
            Ks[r*KS32 + c4*2    ] = pack_bf16x2(v.x, v.y);
            Ks[r*KS32 + c4*2 + 1] = pack_bf16x2(v.z, v.w);
        }
#pragma unroll
        for (int p = 0; p < 2; p++) {
            int idx = tid + p*256;
            int sp = idx & 31, dg = idx >> 5;
            int d0 = dg * 4;
            float4 v0 = *(const float4*)&vbase[(size_t)(kt + 2*sp    )*3*CC + d0];
            float4 v1 = *(const float4*)&vbase[(size_t)(kt + 2*sp + 1)*3*CC + d0];
            Vt[(d0    )*VS32 + sp] = pack_bf16x2(v0.x, v1.x);
            Vt[(d0 + 1)*VS32 + sp] = pack_bf16x2(v0.y, v1.y);
            Vt[(d0 + 2)*VS32 + sp] = pack_bf16x2(v0.z, v1.z);
            Vt[(d0 + 3)*VS32 + sp] = pack_bf16x2(v0.w, v1.w);
        }
        __syncthreads();

        float s[8][4];
#pragma unroll
        for (int nf = 0; nf < 8; nf++)
#pragma unroll
            for (int j = 0; j < 4; j++) s[nf][j] = 0.f;

#pragma unroll
        for (int c = 0; c < 4; c++) {
            int c8 = c * 8;
            uint32_t aq[4];
            aq[0] = Qs[(wr+g  )*QS32 + c8 + tg    ];
            aq[1] = Qs[(wr+g+8)*QS32 + c8 + tg    ];
            aq[2] = Qs[(wr+g  )*QS32 + c8 + tg + 4];
            aq[3] = Qs[(wr+g+8)*QS32 + c8 + tg + 4];
#pragma unroll
            for (int nf = 0; nf < 8; nf++) {
                uint32_t bk[2];
                bk[0] = Ks[(nf*8+g)*KS32 + c8 + tg    ];
                bk[1] = Ks[(nf*8+g)*KS32 + c8 + tg + 4];
                MMA_BF16(s[nf], aq, bk);
            }
        }

#pragma unroll
        for (int nf = 0; nf < 8; nf++) {
            if (nf < 4) {
                s[nf][0] = ex2_mufu(fminf(s[nf][0], 80.f));
                s[nf][1] = ex2_mufu(fminf(s[nf][1], 80.f));
                s[nf][2] = ex2_mufu(fminf(s[nf][2], 80.f));
                s[nf][3] = ex2_mufu(fminf(s[nf][3], 80.f));
            } else {
                s[nf][0] = ex2_poly(fminf(fmaxf(s[nf][0], -80.f), 80.f));
                s[nf][1] = ex2_poly(fminf(fmaxf(s[nf][1], -80.f), 80.f));
                s[nf][2] = ex2_poly(fminf(fmaxf(s[nf][2], -80.f), 80.f));
                s[nf][3] = ex2_poly(fminf(fmaxf(s[nf][3], -80.f), 80.f));
            }
            lsum0 += s[nf][0] + s[nf][1];
            lsum1 += s[nf][2] + s[nf][3];
        }

#pragma unroll
        for (int j = 0; j < 4; j++) {
            uint32_t ap[4];
            ap[0] = pack_bf16x2(s[2*j  ][0], s[2*j  ][1]);
            ap[1] = pack_bf16x2(s[2*j  ][2], s[2*j  ][3]);
            ap[2] = pack_bf16x2(s[2*j+1][0], s[2*j+1][1]);
            ap[3] = pack_bf16x2(s[2*j+1][2], s[2*j+1][3]);
            int c8 = j * 8;
#pragma unroll
            for (int nf = 0; nf < 8; nf++) {
                uint32_t bv[2];
                bv[0] = Vt[(nf*8+g)*VS32 + c8 + tg    ];
                bv[1] = Vt[(nf*8+g)*VS32 + c8 + tg + 4];
                MMA_BF16(o[nf], ap, bv);
            }
        }
        __syncthreads();
    }

    lsum0 += __shfl_xor_sync(0xffffffffu, lsum0, 1);
    lsum0 += __shfl_xor_sync(0xffffffffu, lsum0, 2);
    lsum1 += __shfl_xor_sync(0xffffffffu, lsum1, 1);
    lsum1 += __shfl_xor_sync(0xffffffffu, lsum1, 2);
    float inv0 = 1.0f / lsum0, inv1 = 1.0f / lsum1;

    int row0 = b*TT + tq0 + wr + g;
#pragma unroll
    for (int nf = 0; nf < 8; nf++) {
        int col = h*HS + nf*8 + 2*tg;
        float2 v0 = make_float2(to_tf32(o[nf][0]*inv0), to_tf32(o[nf][1]*inv0));
        float2 v1 = make_float2(to_tf32(o[nf][2]*inv1), to_tf32(o[nf][3]*inv1));
        *(float2*)&g_attn[(size_t)row0*CC + col]     = v0;
        *(float2*)&g_attn[(size_t)(row0+8)*CC + col] = v1;
    }
}

// ---------------------------------------------------------------------------
// Launch
// ---------------------------------------------------------------------------
extern "C" void kernel_launch(void* const* d_in, const int* in_sizes, int n_in,
                              void* d_out, int out_size) {
    const float* x      = (const float*)d_in[0];
    const float* Wq     = (const float*)d_in[1];
    const float* bq     = (const float*)d_in[2];
    const float* Wk     = (const float*)d_in[3];
    const float* bk     = (const float*)d_in[4];
    const float* Wv     = (const float*)d_in[5];
    const float* bv     = (const float*)d_in[6];
    const float* Wo     = (const float*)d_in[7];
    const float* bo     = (const float*)d_in[8];
    const float* W1     = (const float*)d_in[9];
    const float* b1     = (const float*)d_in[10];
    const float* W2     = (const float*)d_in[11];
    const float* b2     = (const float*)d_in[12];
    const float* gamma1 = (const float*)d_in[13];
    const float* beta1  = (const float*)d_in[14];
    const float* gamma2 = (const float*)d_in[15];
    const float* beta2  = (const float*)d_in[16];
    float* out = (float*)d_out;

    float *p_h, *p_wqkv, *p_bqkv, *p_qkv, *p_attn, *p_x1, *p_h2, *p_ff;
    float *p_wor, *p_w1r, *p_w2r;
    cudaGetSymbolAddress((void**)&p_h,    g_h);
    cudaGetSymbolAddress((void**)&p_wqkv, g_wqkv);
    cudaGetSymbolAddress((void**)&p_bqkv, g_bqkv);
    cudaGetSymbolAddress((void**)&p_qkv,  g_qkv);
    cudaGetSymbolAddress((void**)&p_attn, g_attn);
    cudaGetSymbolAddress((void**)&p_x1,   g_x1);
    cudaGetSymbolAddress((void**)&p_h2,   g_h2);
    cudaGetSymbolAddress((void**)&p_ff,   g_ff);
    cudaGetSymbolAddress((void**)&p_wor,  g_wor);
    cudaGetSymbolAddress((void**)&p_w1r,  g_w1r);
    cudaGetSymbolAddress((void**)&p_w2r,  g_w2r);

    cudaFuncSetAttribute(attn_tc_kernel,
                         cudaFuncAttributeMaxDynamicSharedMemorySize, ATTN_SMEM);
    cudaFuncSetAttribute(gemm_tc_kernel<1,0,0,0>,
                         cudaFuncAttributeMaxDynamicSharedMemorySize, GEMM_SMEM);
    cudaFuncSetAttribute(gemm_tc_kernel<1,0,1,0>,
                         cudaFuncAttributeMaxDynamicSharedMemorySize, GEMM_SMEM);
    cudaFuncSetAttribute(gemm_tc_kernel<1,1,0,1>,
                         cudaFuncAttributeMaxDynamicSharedMemorySize, GEMM_SMEM);

    // 0. weight permutes (fragment-pair layout, tf32-rounded)
    pack_qkv_perm_kernel<<<dim3(CC/32, HH), 256>>>(Wq, Wk, Wv);
    pack_bias_kernel<<<(CC + 255)/256, 256>>>(bq, bk, bv);
    permute_w_kernel<<<dim3(CC/64,   CC/32),  256>>>(Wo, p_wor, CC,   CC);
    permute_w_kernel<<<dim3(4*CC/64, CC/32),  256>>>(W1, p_w1r, CC,   4*CC);
    permute_w_kernel<<<dim3(CC/64,   4*CC/32),256>>>(W2, p_w2r, 4*CC, CC);

    // 1. LN1
    ln_seq_kernel<<<dim3(CC/32, BB), dim3(32, 32)>>>(x, gamma1, beta1, p_h);

    // 2. QKV GEMM: [4096,1024] @ [1024,3072]
    gemm_tc_kernel<1,0,0,0><<<dim3(3*CC/128, NROWS/256), 256, GEMM_SMEM>>>(
        p_h, p_wqkv, p_bqkv, nullptr, p_qkv, NROWS, 3*CC, CC);

    // 3. attention
    attn_tc_kernel<<<dim3(TT/128, HH, BB), 256, ATTN_SMEM>>>();

    // 4. output projection + residual
    gemm_tc_kernel<1,0,1,0><<<dim3(CC/128, NROWS/256), 256, GEMM_SMEM>>>(
        p_attn, p_wor, bo, x, p_x1, NROWS, CC, CC);

    // 5. LN2
    ln_seq_kernel<<<dim3(CC/32, BB), dim3(32, 32)>>>(p_x1, gamma2, beta2, p_h2);

    // 6. FF1 + relu (rounded output)
    gemm_tc_kernel<1,1,0,1><<<dim3(4*CC/128, NROWS/256), 256, GEMM_SMEM>>>(
        p_h2, p_w1r, b1, nullptr, p_ff, NROWS, 4*CC, CC);

    // 7. FF2 + residual -> out
    gemm_tc_kernel<1,0,1,0><<<dim3(CC/128, NROWS/256), 256, GEMM_SMEM>>>(
        p_ff, p_w2r, b2, p_x1, out, NROWS, CC, 4*CC);
}

// round 10
// speedup vs baseline: 1.0513x; 1.0513x over previous
#include <cuda_runtime.h>
#include <math.h>
#include <stdint.h>

// Problem constants
#define BB 2
#define TT 2048
#define CC 1024
#define HH 16
#define HS 64
#define NROWS (BB*TT)        // 4096
#define LN_EPS 1e-5f

// ---------------------------------------------------------------------------
// Scratch
// ---------------------------------------------------------------------------
__device__ float g_h   [NROWS*CC];
__device__ float g_wqkv[CC*3*CC];      // PERMUTED qkv weight (q-major frag pairs)
__device__ float g_bqkv[3*CC];
__device__ float g_qkv [NROWS*3*CC];
__device__ float g_attn[NROWS*CC];
__device__ float g_x1  [NROWS*CC];
__device__ float g_h2  [NROWS*CC];
__device__ float g_ff  [NROWS*4*CC];
__device__ float g_wor [CC*CC];        // permuted Wo
__device__ float g_w1r [CC*4*CC];      // permuted W1
__device__ float g_w2r [4*CC*CC];      // permuted W2

__device__ __forceinline__ float to_tf32(float x) {
    uint32_t u;
    asm("cvt.rna.tf32.f32 %0, %1;" : "=r"(u) : "f"(x));
    return __uint_as_float(u);
}
__device__ __forceinline__ float ex2_mufu(float y) {
    float r;
    asm("ex2.approx.ftz.f32 %0, %1;" : "=f"(r) : "f"(y));
    return r;
}
__device__ __forceinline__ float ex2_poly(float y) {
    float r = y + 12582912.f;
    int   n = __float_as_int(r);
    float t = r - 12582912.f;
    float f = y - t;
    float p = 0.00961813f;
    p = fmaf(p, f, 0.05550411f);
    p = fmaf(p, f, 0.24022651f);
    p = fmaf(p, f, 0.69314718f);
    p = fmaf(p, f, 1.0f);
    return __int_as_float(__float_as_int(p) + (n << 23));
}
__device__ __forceinline__ uint32_t pack_bf16x2(float lo, float hi) {
    uint32_t r;
    asm("cvt.rn.bf16x2.f32 %0, %1, %2;" : "=r"(r) : "f"(hi), "f"(lo));
    return r;
}
__device__ __forceinline__ void cp16(uint32_t dst, const void* src) {
    asm volatile("cp.async.cg.shared.global [%0], [%1], 16;\n"
                 :: "r"(dst), "l"(src));
}
#define CP_COMMIT() asm volatile("cp.async.commit_group;\n" ::: "memory")
#define CP_WAIT(n)  asm volatile("cp.async.wait_group %0;\n" :: "n"(n) : "memory")

// ---------------------------------------------------------------------------
// Weight permute: B[K,N] row-major -> q-major fragment-pair layout.
// dst (as float2): [((k0/32)*16 + q)*N + n],  q = ks*4+tg,
//   value = (tf32(B[k0+8ks+tg][n]), tf32(B[k0+8ks+tg+4][n]))
// grid (N/64, K/32), block 256, smem tile 32x64 (stride 68: float4-safe)
// ---------------------------------------------------------------------------
__global__ void permute_w_kernel(const float* __restrict__ src,
                                 float* __restrict__ dst, int K, int N) {
    __shared__ float smw[32][68];
    int n0 = blockIdx.x * 64, k0 = blockIdx.y * 32;
    int tid = threadIdx.x;
    int r = tid >> 3, c8 = (tid & 7) * 8;
    {
        float4 v0 = *(const float4*)&src[(size_t)(k0 + r)*N + n0 + c8];
        float4 v1 = *(const float4*)&src[(size_t)(k0 + r)*N + n0 + c8 + 4];
        *(float4*)&smw[r][c8]     = v0;
        *(float4*)&smw[r][c8 + 4] = v1;
    }
    __syncthreads();
    float2* d2 = (float2*)dst;
#pragma unroll
    for (int p = 0; p < 4; p++) {
        int idx = tid + p*256;          // 1024 = 64 n x 16 q
        int nl = idx >> 4, q = idx & 15;
        int ks = q >> 2, tg = q & 3;
        float2 v;
        v.x = to_tf32(smw[8*ks + tg    ][nl]);
        v.y = to_tf32(smw[8*ks + tg + 4][nl]);
        d2[((size_t)(k0 >> 5)*16 + q)*N + n0 + nl] = v;
    }
}

// ---------------------------------------------------------------------------
// QKV weight pack+permute: Wq/Wk/Wv [H,C,HS] -> g_wqkv q-major fragment layout
// (B matrix [K=C, N=3C], n = w*1024 + h*64 + d).  grid (CC/32, HH), block 256
// ---------------------------------------------------------------------------
__global__ void pack_qkv_perm_kernel(const float* __restrict__ Wq,
                                     const float* __restrict__ Wk,
                                     const float* __restrict__ Wv) {
    __shared__ float smw[32][68];
    int c0 = blockIdx.x * 32, h = blockIdx.y;
    int tid = threadIdx.x;
    int r = tid >> 3, c8 = (tid & 7) * 8;
    const float* srcs[3] = {Wq, Wk, Wv};
    float2* d2 = (float2*)g_wqkv;
    const int N = 3*CC;
#pragma unroll
    for (int m = 0; m < 3; m++) {
        const float* s = srcs[m] + ((size_t)h*CC + c0)*HS;
        {
            float4 v0 = *(const float4*)&s[(size_t)r*HS + c8];
            float4 v1 = *(const float4*)&s[(size_t)r*HS + c8 + 4];
            *(float4*)&smw[r][c8]     = v0;
            *(float4*)&smw[r][c8 + 4] = v1;
        }
        __syncthreads();
#pragma unroll
        for (int p = 0; p < 4; p++) {
            int idx = tid + p*256;
            int nl = idx >> 4, q = idx & 15;
            int ks = q >> 2, tg = q & 3;
            float2 v;
            v.x = to_tf32(smw[8*ks + tg    ][nl]);
            v.y = to_tf32(smw[8*ks + tg + 4][nl]);
            int n = m*CC + h*HS + nl;
            d2[((size_t)(c0 >> 5)*16 + q)*N + n] = v;
        }
        __syncthreads();
    }
}

__global__ void pack_bias_kernel(const float* __restrict__ bq,
                                 const float* __restrict__ bk,
                                 const float* __restrict__ bv) {
    int e = blockIdx.x * blockDim.x + threadIdx.x;
    if (e < CC) {
        g_bqkv[e]        = bq[e];
        g_bqkv[CC + e]   = bk[e];
        g_bqkv[2*CC + e] = bv[e];
    }
}

// ---------------------------------------------------------------------------
// LayerNorm over sequence axis (tf32-rounded output)
// ---------------------------------------------------------------------------
__global__ void __launch_bounds__(1024)
ln_seq_kernel(const float* __restrict__ x,
              const float* __restrict__ gamma,
              const float* __restrict__ beta,
              float* __restrict__ out) {
    int b  = blockIdx.y;
    int tx = threadIdx.x, ty = threadIdx.y;
    int c  = blockIdx.x * 32 + tx;
    const float* xp = x   + (size_t)b*TT*CC + c;
    float*       op = out + (size_t)b*TT*CC + c;

    float s = 0.f, sq = 0.f;
    for (int t = ty; t < TT; t += 32) {
        float v = xp[(size_t)t*CC];
        s += v; sq += v*v;
    }
    __shared__ float ssum[32][33];
    __shared__ float ssq [32][33];
    ssum[ty][tx] = s; ssq[ty][tx] = sq;
    __syncthreads();
    for (int off = 16; off > 0; off >>= 1) {
        if (ty < off) {
            ssum[ty][tx] += ssum[ty+off][tx];
            ssq [ty][tx] += ssq [ty+off][tx];
        }
        __syncthreads();
    }
    __shared__ float meanv[32], rstdv[32];
    if (ty == 0) {
        float mean = ssum[0][tx] * (1.0f / TT);
        float var  = (ssq[0][tx] - (float)TT * mean * mean) * (1.0f / (TT - 1));
        meanv[tx]  = mean;
        rstdv[tx]  = 1.0f / (sqrtf(var) + LN_EPS);
    }
    __syncthreads();
    float mean = meanv[tx], rstd = rstdv[tx];
    float g = gamma[c], bt = beta[c];
    for (int t = ty; t < TT; t += 32) {
        float v = xp[(size_t)t*CC];
        op[(size_t)t*CC] = to_tf32(g * ((v - mean) * rstd) + bt);
    }
}

// ---------------------------------------------------------------------------
// TF32 GEMM, 128x128 block tile (R6 shape), 8 warps (4m x 2n), warp 32x64.
// A row-major; B q-major fragment-pair layout (one LDS.64 per B frag).
// 2-stage cp.async double buffering; 2 CTAs/SM.
// ---------------------------------------------------------------------------
#define MMA_TF32(d, a, b)                                                     \
    asm volatile(                                                             \
        "mma.sync.aligned.m16n8k8.row.col.f32.tf32.tf32.f32 "                 \
        "{%0,%1,%2,%3},{%4,%5,%6,%7},{%8,%9},{%0,%1,%2,%3};\n"                \
        : "+f"((d)[0]), "+f"((d)[1]), "+f"((d)[2]), "+f"((d)[3])              \
        : "r"((a)[0]), "r"((a)[1]), "r"((a)[2]), "r"((a)[3]),                 \
          "r"((b)[0]), "r"((b)[1]))

#define AS_FLOATS (128*36)     /* 4608 per buffer */
#define BS_FLOATS (16*132*2)   /* 4224 per buffer: [q=0..15][n=0..127] float2 */
#define GEMM_SMEM ((2*AS_FLOATS + 2*BS_FLOATS)*4)   /* 70656 B */

template<int DOBIAS, int DORELU, int DORES, int DOROUND>
__global__ void __launch_bounds__(256, 2)
gemm_tc_kernel(const float* __restrict__ A, const float* __restrict__ Bm,
               const float* __restrict__ bias, const float* __restrict__ res,
               float* __restrict__ Cm, int M, int N, int K) {
    extern __shared__ float smg[];
    int tid  = threadIdx.x;
    int lane = tid & 31, wid = tid >> 5;
    int wm = (wid >> 1) * 32;        // 4 m-warps
    int wn = (wid & 1) * 64;         // 2 n-warps
    int g  = lane >> 2;
    int tg = lane & 3;
    int m0 = blockIdx.y * 128, n0 = blockIdx.x * 128;

    float acc[2][8][4];
#pragma unroll
    for (int mf = 0; mf < 2; mf++)
#pragma unroll
        for (int nf = 0; nf < 8; nf++)
#pragma unroll
            for (int r = 0; r < 4; r++) acc[mf][nf][r] = 0.f;

    uint32_t smg_u = (uint32_t)__cvta_generic_to_shared(smg);
    int nk = K >> 5;

    int ar = tid >> 3, ac = (tid & 7) * 4;    // A: 4 passes of 32 rows
    // B staging: 1024 cp16 = 4 passes; idx -> q = idx>>6 (0..15), n = (idx&63)*2

    // prologue: stage 0
    {
        uint32_t as_b = smg_u;
        uint32_t bs_b = smg_u + (2*AS_FLOATS)*4;
#pragma unroll
        for (int p = 0; p < 4; p++)
            cp16(as_b + ((ar + 32*p)*36 + ac)*4,
                 &A[(size_t)(m0 + ar + 32*p)*K + ac]);
        const float2* bsrc = (const float2*)Bm + (size_t)n0;   // k-chunk 0
#pragma unroll
        for (int p = 0; p < 4; p++) {
            int idx = tid + 256*p;
            int q = idx >> 6, n = (idx & 63) * 2;
            cp16(bs_b + (q*132 + n)*8, bsrc + (size_t)q*N + n);
        }
        CP_COMMIT();
    }

    for (int i = 0; i < nk; i++) {
        int buf = i & 1;
        if (i + 1 < nk) {
            int nb = (i + 1) & 1;
            uint32_t as_b = smg_u + (nb*AS_FLOATS)*4;
            uint32_t bs_b = smg_u + (2*AS_FLOATS + nb*BS_FLOATS)*4;
            int k0 = (i + 1) << 5;
#pragma unroll
            for (int p = 0; p < 4; p++)
                cp16(as_b + ((ar + 32*p)*36 + ac)*4,
                     &A[(size_t)(m0 + ar + 32*p)*K + k0 + ac]);
            const float2* bsrc = (const float2*)Bm
                                 + ((size_t)(k0 >> 5)*16)*N + n0;
#pragma unroll
            for (int p = 0; p < 4; p++) {
                int idx = tid + 256*p;
                int q = idx >> 6, n = (idx & 63) * 2;
                cp16(bs_b + (q*132 + n)*8, bsrc + (size_t)q*N + n);
            }
            CP_COMMIT();
            CP_WAIT(1);
        } else {
            CP_WAIT(0);
        }
        __syncthreads();

        const float* As = smg + buf*AS_FLOATS;
        const float* Bs = smg + 2*AS_FLOATS + buf*BS_FLOATS;

#pragma unroll
        for (int ks = 0; ks < 4; ks++) {
            int kk = ks * 8;
            uint32_t afr[2][4];
#pragma unroll
            for (int mf = 0; mf < 2; mf++) {
                int r = wm + mf*16 + g;
                afr[mf][0] = __float_as_uint(As[(r    )*36 + kk + tg    ]);
                afr[mf][1] = __float_as_uint(As[(r + 8)*36 + kk + tg    ]);
                afr[mf][2] = __float_as_uint(As[(r    )*36 + kk + tg + 4]);
                afr[mf][3] = __float_as_uint(As[(r + 8)*36 + kk + tg + 4]);
            }
#pragma unroll
            for (int nf = 0; nf < 8; nf++) {
                int n = wn + nf*8 + g;
                float2 bp = *(const float2*)&Bs[((ks*4 + tg)*132 + n)*2];
                uint32_t bfr[2];
                bfr[0] = __float_as_uint(bp.x);
                bfr[1] = __float_as_uint(bp.y);
#pragma unroll
                for (int mf = 0; mf < 2; mf++)
                    MMA_TF32(acc[mf][nf], afr[mf], bfr);
            }
        }
        __syncthreads();
    }

#pragma unroll
    for (int mf = 0; mf < 2; mf++) {
#pragma unroll
        for (int nf = 0; nf < 8; nf++) {
            int r  = m0 + wm + mf*16 + g;
            int cb = n0 + wn + nf*8 + 2*tg;
            float2 v0 = make_float2(acc[mf][nf][0], acc[mf][nf][1]);
            float2 v1 = make_float2(acc[mf][nf][2], acc[mf][nf][3]);
            if (DOBIAS) {
                float2 bsv = *(const float2*)&bias[cb];
                v0.x += bsv.x; v0.y += bsv.y;
                v1.x += bsv.x; v1.y += bsv.y;
            }
            if (DORELU) {
                v0.x = fmaxf(v0.x, 0.f); v0.y = fmaxf(v0.y, 0.f);
                v1.x = fmaxf(v1.x, 0.f); v1.y = fmaxf(v1.y, 0.f);
            }
            if (DORES) {
                float2 r0 = *(const float2*)&res[(size_t)r*N + cb];
                float2 r1 = *(const float2*)&res[(size_t)(r+8)*N + cb];
                v0.x += r0.x; v0.y += r0.y;
                v1.x += r1.x; v1.y += r1.y;
            }
            if (DOROUND) {
                v0.x = to_tf32(v0.x); v0.y = to_tf32(v0.y);
                v1.x = to_tf32(v1.x); v1.y = to_tf32(v1.y);
            }
            *(float2*)&Cm[(size_t)r*N + cb]     = v0;
            *(float2*)&Cm[(size_t)(r+8)*N + cb] = v1;
        }
    }
}

// ---------------------------------------------------------------------------
// bf16 tensor-core flash attention (verified R6)
// ---------------------------------------------------------------------------
#define QS32 36
#define KS32 36
#define VS32 36
#define SM32_QS 0
#define SM32_KS (128*QS32)
#define SM32_VT (SM32_KS + 64*KS32)
#define ATTN_SMEM ((SM32_VT + 64*VS32)*4)
#define QSCALE 0.18033688f

#define MMA_BF16(d, a, b)                                                     \
    asm volatile(                                                             \
        "mma.sync.aligned.m16n8k16.row.col.f32.bf16.bf16.f32 "                \
        "{%0,%1,%2,%3},{%4,%5,%6,%7},{%8,%9},{%0,%1,%2,%3};\n"                \
        : "+f"((d)[0]), "+f"((d)[1]), "+f"((d)[2]), "+f"((d)[3])              \
        : "r"((a)[0]), "r"((a)[1]), "r"((a)[2]), "r"((a)[3]),                 \
          "r"((b)[0]), "r"((b)[1]))

__global__ void __launch_bounds__(256, 2) attn_tc_kernel() {
    extern __shared__ uint32_t smu[];
    uint32_t* Qs = smu + SM32_QS;
    uint32_t* Ks = smu + SM32_KS;
    uint32_t* Vt = smu + SM32_VT;

    int tid = threadIdx.x, lane = tid & 31, wid = tid >> 5;
    int g = lane >> 2, tg = lane & 3;
    int b = blockIdx.z, h = blockIdx.y;
    int tq0 = blockIdx.x * 128;
    int wr = wid * 16;

    const float* qbase = g_qkv + (size_t)b*TT*3*CC + (size_t)h*HS;
    const float* kbase = qbase + CC;
    const float* vbase = qbase + 2*CC;

#pragma unroll
    for (int p = 0; p < 8; p++) {
        int idx = tid + p*256;
        int r = idx >> 4, c4 = idx & 15;
        float4 v = *(const float4*)&qbase[(size_t)(tq0 + r)*3*CC + c4*4];
        Qs[r*QS32 + c4*2    ] = pack_bf16x2(v.x*QSCALE, v.y*QSCALE);
        Qs[r*QS32 + c4*2 + 1] = pack_bf16x2(v.z*QSCALE, v.w*QSCALE);
    }

    float o[8][4];
#pragma unroll
    for (int i = 0; i < 8; i++)
#pragma unroll
        for (int j = 0; j < 4; j++) o[i][j] = 0.f;
    float lsum0 = 0.f, lsum1 = 0.f;

    __syncthreads();

    for (int kt = 0; kt < TT; kt += 64) {
#pragma unroll
        for (int p = 0; p < 4; p++) {
            int idx = tid + p*256;
            int r = idx >> 4, c4 = idx & 15;
            float4 v = *(const float4*)&kbase[(size_t)(kt + r)*3*CC + c4*4];
            Ks[r*KS32 + c4*2    ] = pack_bf16x2(v.x, v.y);
            Ks[r*KS32 + c4*2 + 1] = pack_bf16x2(v.z, v.w);
        }
#pragma unroll
        for (int p = 0; p < 2; p++) {
            int idx = tid + p*256;
            int sp = idx & 31, dg = idx >> 5;
            int d0 = dg * 4;
            float4 v0 = *(const float4*)&vbase[(size_t)(kt + 2*sp    )*3*CC + d0];
            float4 v1 = *(const float4*)&vbase[(size_t)(kt + 2*sp + 1)*3*CC + d0];
            Vt[(d0    )*VS32 + sp] = pack_bf16x2(v0.x, v1.x);
            Vt[(d0 + 1)*VS32 + sp] = pack_bf16x2(v0.y, v1.y);
            Vt[(d0 + 2)*VS32 + sp] = pack_bf16x2(v0.z, v1.z);
            Vt[(d0 + 3)*VS32 + sp] = pack_bf16x2(v0.w, v1.w);
        }
        __syncthreads();

        float s[8][4];
#pragma unroll
        for (int nf = 0; nf < 8; nf++)
#pragma unroll
            for (int j = 0; j < 4; j++) s[nf][j] = 0.f;

#pragma unroll
        for (int c = 0; c < 4; c++) {
            int c8 = c * 8;
            uint32_t aq[4];
            aq[0] = Qs[(wr+g  )*QS32 + c8 + tg    ];
            aq[1] = Qs[(wr+g+8)*QS32 + c8 + tg    ];
            aq[2] = Qs[(wr+g  )*QS32 + c8 + tg + 4];
            aq[3] = Qs[(wr+g+8)*QS32 + c8 + tg + 4];
#pragma unroll
            for (int nf = 0; nf < 8; nf++) {
                uint32_t bk[2];
                bk[0] = Ks[(nf*8+g)*KS32 + c8 + tg    ];
                bk[1] = Ks[(nf*8+g)*KS32 + c8 + tg + 4];
                MMA_BF16(s[nf], aq, bk);
            }
        }

#pragma unroll
        for (int nf = 0; nf < 8; nf++) {
            if (nf < 4) {
                s[nf][0] = ex2_mufu(fminf(s[nf][0], 80.f));
                s[nf][1] = ex2_mufu(fminf(s[nf][1], 80.f));
                s[nf][2] = ex2_mufu(fminf(s[nf][2], 80.f));
                s[nf][3] = ex2_mufu(fminf(s[nf][3], 80.f));
            } else {
                s[nf][0] = ex2_poly(fminf(fmaxf(s[nf][0], -80.f), 80.f));
                s[nf][1] = ex2_poly(fminf(fmaxf(s[nf][1], -80.f), 80.f));
                s[nf][2] = ex2_poly(fminf(fmaxf(s[nf][2], -80.f), 80.f));
                s[nf][3] = ex2_poly(fminf(fmaxf(s[nf][3], -80.f), 80.f));
            }
            lsum0 += s[nf][0] + s[nf][1];
            lsum1 += s[nf][2] + s[nf][3];
        }

#pragma unroll
        for (int j = 0; j < 4; j++) {
            uint32_t ap[4];
            ap[0] = pack_bf16x2(s[2*j  ][0], s[2*j  ][1]);
            ap[1] = pack_bf16x2(s[2*j  ][2], s[2*j  ][3]);
            ap[2] = pack_bf16x2(s[2*j+1][0], s[2*j+1][1]);
            ap[3] = pack_bf16x2(s[2*j+1][2], s[2*j+1][3]);
            int c8 = j * 8;
#pragma unroll
            for (int nf = 0; nf < 8; nf++) {
                uint32_t bv[2];
                bv[0] = Vt[(nf*8+g)*VS32 + c8 + tg    ];
                bv[1] = Vt[(nf*8+g)*VS32 + c8 + tg + 4];
                MMA_BF16(o[nf], ap, bv);
            }
        }
        __syncthreads();
    }

    lsum0 += __shfl_xor_sync(0xffffffffu, lsum0, 1);
    lsum0 += __shfl_xor_sync(0xffffffffu, lsum0, 2);
    lsum1 += __shfl_xor_sync(0xffffffffu, lsum1, 1);
    lsum1 += __shfl_xor_sync(0xffffffffu, lsum1, 2);
    float inv0 = 1.0f / lsum0, inv1 = 1.0f / lsum1;

    int row0 = b*TT + tq0 + wr + g;
#pragma unroll
    for (int nf = 0; nf < 8; nf++) {
        int col = h*HS + nf*8 + 2*tg;
        float2 v0 = make_float2(to_tf32(o[nf][0]*inv0), to_tf32(o[nf][1]*inv0));
        float2 v1 = make_float2(to_tf32(o[nf][2]*inv1), to_tf32(o[nf][3]*inv1));
        *(float2*)&g_attn[(size_t)row0*CC + col]     = v0;
        *(float2*)&g_attn[(size_t)(row0+8)*CC + col] = v1;
    }
}

// ---------------------------------------------------------------------------
// Launch
// ---------------------------------------------------------------------------
extern "C" void kernel_launch(void* const* d_in, const int* in_sizes, int n_in,
                              void* d_out, int out_size) {
    const float* x      = (const float*)d_in[0];
    const float* Wq     = (const float*)d_in[1];
    const float* bq     = (const float*)d_in[2];
    const float* Wk     = (const float*)d_in[3];
    const float* bk     = (const float*)d_in[4];
    const float* Wv     = (const float*)d_in[5];
    const float* bv     = (const float*)d_in[6];
    const float* Wo     = (const float*)d_in[7];
    const float* bo     = (const float*)d_in[8];
    const float* W1     = (const float*)d_in[9];
    const float* b1     = (const float*)d_in[10];
    const float* W2     = (const float*)d_in[11];
    const float* b2     = (const float*)d_in[12];
    const float* gamma1 = (const float*)d_in[13];
    const float* beta1  = (const float*)d_in[14];
    const float* gamma2 = (const float*)d_in[15];
    const float* beta2  = (const float*)d_in[16];
    float* out = (float*)d_out;

    float *p_h, *p_wqkv, *p_bqkv, *p_qkv, *p_attn, *p_x1, *p_h2, *p_ff;
    float *p_wor, *p_w1r, *p_w2r;
    cudaGetSymbolAddress((void**)&p_h,    g_h);
    cudaGetSymbolAddress((void**)&p_wqkv, g_wqkv);
    cudaGetSymbolAddress((void**)&p_bqkv, g_bqkv);
    cudaGetSymbolAddress((void**)&p_qkv,  g_qkv);
    cudaGetSymbolAddress((void**)&p_attn, g_attn);
    cudaGetSymbolAddress((void**)&p_x1,   g_x1);
    cudaGetSymbolAddress((void**)&p_h2,   g_h2);
    cudaGetSymbolAddress((void**)&p_ff,   g_ff);
    cudaGetSymbolAddress((void**)&p_wor,  g_wor);
    cudaGetSymbolAddress((void**)&p_w1r,  g_w1r);
    cudaGetSymbolAddress((void**)&p_w2r,  g_w2r);

    cudaFuncSetAttribute(attn_tc_kernel,
                         cudaFuncAttributeMaxDynamicSharedMemorySize, ATTN_SMEM);
    cudaFuncSetAttribute(gemm_tc_kernel<1,0,0,0>,
                         cudaFuncAttributeMaxDynamicSharedMemorySize, GEMM_SMEM);
    cudaFuncSetAttribute(gemm_tc_kernel<1,0,1,0>,
                         cudaFuncAttributeMaxDynamicSharedMemorySize, GEMM_SMEM);
    cudaFuncSetAttribute(gemm_tc_kernel<1,1,0,1>,
                         cudaFuncAttributeMaxDynamicSharedMemorySize, GEMM_SMEM);

    // 0. weight permutes (q-major fragment layout, tf32-rounded)
    pack_qkv_perm_kernel<<<dim3(CC/32, HH), 256>>>(Wq, Wk, Wv);
    pack_bias_kernel<<<(CC + 255)/256, 256>>>(bq, bk, bv);
    permute_w_kernel<<<dim3(CC/64,   CC/32),  256>>>(Wo, p_wor, CC,   CC);
    permute_w_kernel<<<dim3(4*CC/64, CC/32),  256>>>(W1, p_w1r, CC,   4*CC);
    permute_w_kernel<<<dim3(CC/64,   4*CC/32),256>>>(W2, p_w2r, 4*CC, CC);

    // 1. LN1
    ln_seq_kernel<<<dim3(CC/32, BB), dim3(32, 32)>>>(x, gamma1, beta1, p_h);

    // 2. QKV GEMM: [4096,1024] @ [1024,3072]
    gemm_tc_kernel<1,0,0,0><<<dim3(3*CC/128, NROWS/128), 256, GEMM_SMEM>>>(
        p_h, p_wqkv, p_bqkv, nullptr, p_qkv, NROWS, 3*CC, CC);

    // 3. attention
    attn_tc_kernel<<<dim3(TT/128, HH, BB), 256, ATTN_SMEM>>>();

    // 4. output projection + residual
    gemm_tc_kernel<1,0,1,0><<<dim3(CC/128, NROWS/128), 256, GEMM_SMEM>>>(
        p_attn, p_wor, bo, x, p_x1, NROWS, CC, CC);

    // 5. LN2
    ln_seq_kernel<<<dim3(CC/32, BB), dim3(32, 32)>>>(p_x1, gamma2, beta2, p_h2);

    // 6. FF1 + relu (rounded output)
    gemm_tc_kernel<1,1,0,1><<<dim3(4*CC/128, NROWS/128), 256, GEMM_SMEM>>>(
        p_h2, p_w1r, b1, nullptr, p_ff, NROWS, 4*CC, CC);

    // 7. FF2 + residual -> out
    gemm_tc_kernel<1,0,1,0><<<dim3(CC/128, NROWS/128), 256, GEMM_SMEM>>>(
        p_ff, p_w2r, b2, p_x1, out, NROWS, CC, 4*CC);
}

// round 11
// speedup vs baseline: 1.1189x; 1.0643x over previous
#include <cuda_runtime.h>
#include <math.h>
#include <stdint.h>

// Problem constants
#define BB 2
#define TT 2048
#define CC 1024
#define HH 16
#define HS 64
#define NROWS (BB*TT)        // 4096
#define LN_EPS 1e-5f

// ---------------------------------------------------------------------------
// Scratch
// ---------------------------------------------------------------------------
__device__ float g_h   [NROWS*CC];
__device__ float g_wqkv[CC*3*CC];      // PERMUTED qkv weight: per 32-k chunk, [n][32]
__device__ float g_bqkv[3*CC];
__device__ float g_qkv [NROWS*3*CC];
__device__ float g_attn[NROWS*CC];
__device__ float g_x1  [NROWS*CC];
__device__ float g_h2  [NROWS*CC];
__device__ float g_ff  [NROWS*4*CC];
__device__ float g_wor [CC*CC];        // permuted Wo
__device__ float g_w1r [CC*4*CC];      // permuted W1
__device__ float g_w2r [4*CC*CC];      // permuted W2

__device__ __forceinline__ float to_tf32(float x) {
    uint32_t u;
    asm("cvt.rna.tf32.f32 %0, %1;" : "=r"(u) : "f"(x));
    return __uint_as_float(u);
}
__device__ __forceinline__ float ex2_mufu(float y) {
    float r;
    asm("ex2.approx.ftz.f32 %0, %1;" : "=f"(r) : "f"(y));
    return r;
}
__device__ __forceinline__ float ex2_poly(float y) {
    float r = y + 12582912.f;
    int   n = __float_as_int(r);
    float t = r - 12582912.f;
    float f = y - t;
    float p = 0.00961813f;
    p = fmaf(p, f, 0.05550411f);
    p = fmaf(p, f, 0.24022651f);
    p = fmaf(p, f, 0.69314718f);
    p = fmaf(p, f, 1.0f);
    return __int_as_float(__float_as_int(p) + (n << 23));
}
__device__ __forceinline__ uint32_t pack_bf16x2(float lo, float hi) {
    uint32_t r;
    asm("cvt.rn.bf16x2.f32 %0, %1, %2;" : "=r"(r) : "f"(hi), "f"(lo));
    return r;
}
__device__ __forceinline__ void cp16(uint32_t dst, const void* src) {
    asm volatile("cp.async.cg.shared.global [%0], [%1], 16;\n"
                 :: "r"(dst), "l"(src));
}
#define CP_COMMIT() asm volatile("cp.async.commit_group;\n" ::: "memory")
#define CP_WAIT(n)  asm volatile("cp.async.wait_group %0;\n" :: "n"(n) : "memory")

#define LDSM_X4(r0, r1, r2, r3, addr)                                         \
    asm volatile("ldmatrix.sync.aligned.m8n8.x4.shared.b16 {%0,%1,%2,%3}, [%4];" \
        : "=r"(r0), "=r"(r1), "=r"(r2), "=r"(r3) : "r"(addr))

// ---------------------------------------------------------------------------
// Weight permute: B[K,N] row-major -> per-32k-chunk n-major transpose.
// dst float index: (k0/32)*N*32 + n*32 + kk,  value = tf32(B[k0+kk][n])
// grid (N/64, K/32), block 256
// ---------------------------------------------------------------------------
__global__ void permute_w_kernel(const float* __restrict__ src,
                                 float* __restrict__ dst, int K, int N) {
    __shared__ float smw[32][68];
    int n0 = blockIdx.x * 64, k0 = blockIdx.y * 32;
    int tid = threadIdx.x;
    int r = tid >> 3, c8 = (tid & 7) * 8;
    {
        float4 v0 = *(const float4*)&src[(size_t)(k0 + r)*N + n0 + c8];
        float4 v1 = *(const float4*)&src[(size_t)(k0 + r)*N + n0 + c8 + 4];
        *(float4*)&smw[r][c8]     = v0;
        *(float4*)&smw[r][c8 + 4] = v1;
    }
    __syncthreads();
    int nl = tid >> 2, j = tid & 3;           // n local 0..63, kk block j*8
    float* dbase = dst + (size_t)(k0 >> 5)*N*32 + (size_t)(n0 + nl)*32 + j*8;
    float4 v0, v1;
    v0.x = to_tf32(smw[j*8+0][nl]); v0.y = to_tf32(smw[j*8+1][nl]);
    v0.z = to_tf32(smw[j*8+2][nl]); v0.w = to_tf32(smw[j*8+3][nl]);
    v1.x = to_tf32(smw[j*8+4][nl]); v1.y = to_tf32(smw[j*8+5][nl]);
    v1.z = to_tf32(smw[j*8+6][nl]); v1.w = to_tf32(smw[j*8+7][nl]);
    *(float4*)&dbase[0] = v0;
    *(float4*)&dbase[4] = v1;
}

// ---------------------------------------------------------------------------
// QKV weight pack+permute: Wq/Wk/Wv [H,C,HS] -> g_wqkv chunked n-major layout
// (B matrix [K=C, N=3C], n = w*1024 + h*64 + d).  grid (CC/32, HH), block 256
// ---------------------------------------------------------------------------
__global__ void pack_qkv_perm_kernel(const float* __restrict__ Wq,
                                     const float* __restrict__ Wk,
                                     const float* __restrict__ Wv) {
    __shared__ float smw[32][68];
    int c0 = blockIdx.x * 32, h = blockIdx.y;
    int tid = threadIdx.x;
    int r = tid >> 3, c8 = (tid & 7) * 8;
    const float* srcs[3] = {Wq, Wk, Wv};
    const int N = 3*CC;
#pragma unroll
    for (int m = 0; m < 3; m++) {
        const float* s = srcs[m] + ((size_t)h*CC + c0)*HS;
        {
            float4 v0 = *(const float4*)&s[(size_t)r*HS + c8];
            float4 v1 = *(const float4*)&s[(size_t)r*HS + c8 + 4];
            *(float4*)&smw[r][c8]     = v0;
            *(float4*)&smw[r][c8 + 4] = v1;
        }
        __syncthreads();
        int nl = tid >> 2, j = tid & 3;
        int n = m*CC + h*HS + nl;
        float* dbase = g_wqkv + (size_t)(c0 >> 5)*N*32 + (size_t)n*32 + j*8;
        float4 v0, v1;
        v0.x = to_tf32(smw[j*8+0][nl]); v0.y = to_tf32(smw[j*8+1][nl]);
        v0.z = to_tf32(smw[j*8+2][nl]); v0.w = to_tf32(smw[j*8+3][nl]);
        v1.x = to_tf32(smw[j*8+4][nl]); v1.y = to_tf32(smw[j*8+5][nl]);
        v1.z = to_tf32(smw[j*8+6][nl]); v1.w = to_tf32(smw[j*8+7][nl]);
        *(float4*)&dbase[0] = v0;
        *(float4*)&dbase[4] = v1;
        __syncthreads();
    }
}

__global__ void pack_bias_kernel(const float* __restrict__ bq,
                                 const float* __restrict__ bk,
                                 const float* __restrict__ bv) {
    int e = blockIdx.x * blockDim.x + threadIdx.x;
    if (e < CC) {
        g_bqkv[e]        = bq[e];
        g_bqkv[CC + e]   = bk[e];
        g_bqkv[2*CC + e] = bv[e];
    }
}

// ---------------------------------------------------------------------------
// LayerNorm over sequence axis (tf32-rounded output)
// ---------------------------------------------------------------------------
__global__ void __launch_bounds__(1024)
ln_seq_kernel(const float* __restrict__ x,
              const float* __restrict__ gamma,
              const float* __restrict__ beta,
              float* __restrict__ out) {
    int b  = blockIdx.y;
    int tx = threadIdx.x, ty = threadIdx.y;
    int c  = blockIdx.x * 32 + tx;
    const float* xp = x   + (size_t)b*TT*CC + c;
    float*       op = out + (size_t)b*TT*CC + c;

    float s = 0.f, sq = 0.f;
    for (int t = ty; t < TT; t += 32) {
        float v = xp[(size_t)t*CC];
        s += v; sq += v*v;
    }
    __shared__ float ssum[32][33];
    __shared__ float ssq [32][33];
    ssum[ty][tx] = s; ssq[ty][tx] = sq;
    __syncthreads();
    for (int off = 16; off > 0; off >>= 1) {
        if (ty < off) {
            ssum[ty][tx] += ssum[ty+off][tx];
            ssq [ty][tx] += ssq [ty+off][tx];
        }
        __syncthreads();
    }
    __shared__ float meanv[32], rstdv[32];
    if (ty == 0) {
        float mean = ssum[0][tx] * (1.0f / TT);
        float var  = (ssq[0][tx] - (float)TT * mean * mean) * (1.0f / (TT - 1));
        meanv[tx]  = mean;
        rstdv[tx]  = 1.0f / (sqrtf(var) + LN_EPS);
    }
    __syncthreads();
    float mean = meanv[tx], rstd = rstdv[tx];
    float g = gamma[c], bt = beta[c];
    for (int t = ty; t < TT; t += 32) {
        float v = xp[(size_t)t*CC];
        op[(size_t)t*CC] = to_tf32(g * ((v - mean) * rstd) + bt);
    }
}

// ---------------------------------------------------------------------------
// TF32 GEMM, 128x128 block tile, 8 warps (4m x 2n), warp 32x64.
// A row-major [m][k]; B n-major per-chunk [n][k].  All frags via ldmatrix.x4.
// 2-stage cp.async double buffering; 2 CTAs/SM.
// ---------------------------------------------------------------------------
#define MMA_TF32(d, a, b)                                                     \
    asm volatile(                                                             \
        "mma.sync.aligned.m16n8k8.row.col.f32.tf32.tf32.f32 "                 \
        "{%0,%1,%2,%3},{%4,%5,%6,%7},{%8,%9},{%0,%1,%2,%3};\n"                \
        : "+f"((d)[0]), "+f"((d)[1]), "+f"((d)[2]), "+f"((d)[3])              \
        : "r"((a)[0]), "r"((a)[1]), "r"((a)[2]), "r"((a)[3]),                 \
          "r"((b)[0]), "r"((b)[1]))

#define AS_FLOATS (128*36)     /* 4608 per buffer: A [m][k] stride 36 */
#define BS_FLOATS (128*36)     /* 4608 per buffer: B [n][k] stride 36 */
#define GEMM_SMEM ((2*AS_FLOATS + 2*BS_FLOATS)*4)   /* 73728 B */

template<int DOBIAS, int DORELU, int DORES, int DOROUND>
__global__ void __launch_bounds__(256, 2)
gemm_tc_kernel(const float* __restrict__ A, const float* __restrict__ Bm,
               const float* __restrict__ bias, const float* __restrict__ res,
               float* __restrict__ Cm, int M, int N, int K) {
    extern __shared__ float smg[];
    int tid  = threadIdx.x;
    int lane = tid & 31, wid = tid >> 5;
    int wm = (wid >> 1) * 32;        // 4 m-warps
    int wn = (wid & 1) * 64;         // 2 n-warps
    int g  = lane >> 2;
    int tg = lane & 3;
    int m0 = blockIdx.y * 128, n0 = blockIdx.x * 128;

    float acc[2][8][4];
#pragma unroll
    for (int mf = 0; mf < 2; mf++)
#pragma unroll
        for (int nf = 0; nf < 8; nf++)
#pragma unroll
            for (int r = 0; r < 4; r++) acc[mf][nf][r] = 0.f;

    uint32_t smg_u = (uint32_t)__cvta_generic_to_shared(smg);
    int nk = K >> 5;

    // staging maps
    int ar = tid >> 3, ac = (tid & 7) * 4;    // A: 4 passes of 32 rows
    // B: 1024 cp16 = 4 passes; idx -> n = idx>>3 (0..127), j = idx&7 (k=j*4)

    // ldmatrix lane address components
    int a_lrow = wm + ((lane >> 3) & 1)*8 + (lane & 7);  // + mf*16
    int a_lcol = (lane >> 4) * 4;                         // + kk
    int b_lrow = wn + ((lane >> 4) & 1)*8 + (lane & 7);  // + nfp*16
    int b_lcol = ((lane >> 3) & 1) * 4;                   // + kk

    // prologue: stage 0
    {
        uint32_t as_b = smg_u;
        uint32_t bs_b = smg_u + (2*AS_FLOATS)*4;
#pragma unroll
        for (int p = 0; p < 4; p++)
            cp16(as_b + ((ar + 32*p)*36 + ac)*4,
                 &A[(size_t)(m0 + ar + 32*p)*K + ac]);
        const float* bsrc = Bm + (size_t)n0*32;   // k-chunk 0
#pragma unroll
        for (int p = 0; p < 4; p++) {
            int idx = tid + 256*p;
            int n = idx >> 3, j = idx & 7;
            cp16(bs_b + (n*36 + j*4)*4, bsrc + (size_t)n*32 + j*4);
        }
        CP_COMMIT();
    }

    for (int i = 0; i < nk; i++) {
        int buf = i & 1;
        if (i + 1 < nk) {
            int nb = (i + 1) & 1;
            uint32_t as_b = smg_u + (nb*AS_FLOATS)*4;
            uint32_t bs_b = smg_u + (2*AS_FLOATS + nb*BS_FLOATS)*4;
            int k0 = (i + 1) << 5;
#pragma unroll
            for (int p = 0; p < 4; p++)
                cp16(as_b + ((ar + 32*p)*36 + ac)*4,
                     &A[(size_t)(m0 + ar + 32*p)*K + k0 + ac]);
            const float* bsrc = Bm + (size_t)(k0 >> 5)*N*32 + (size_t)n0*32;
#pragma unroll
            for (int p = 0; p < 4; p++) {
                int idx = tid + 256*p;
                int n = idx >> 3, j = idx & 7;
                cp16(bs_b + (n*36 + j*4)*4, bsrc + (size_t)n*32 + j*4);
            }
            CP_COMMIT();
            CP_WAIT(1);
        } else {
            CP_WAIT(0);
        }
        __syncthreads();

        uint32_t as_base = smg_u + (buf*AS_FLOATS)*4;
        uint32_t bs_base = smg_u + (2*AS_FLOATS + buf*BS_FLOATS)*4;

#pragma unroll
        for (int ks = 0; ks < 4; ks++) {
            int kk = ks * 8;
            uint32_t afr[2][4];
            uint32_t aoff = ((a_lrow)*36 + kk + a_lcol) * 4;
            LDSM_X4(afr[0][0], afr[0][1], afr[0][2], afr[0][3], as_base + aoff);
            LDSM_X4(afr[1][0], afr[1][1], afr[1][2], afr[1][3],
                    as_base + aoff + 16*36*4);

            uint32_t bfr[8][2];
            uint32_t boff = ((b_lrow)*36 + kk + b_lcol) * 4;
#pragma unroll
            for (int nfp = 0; nfp < 4; nfp++) {
                LDSM_X4(bfr[2*nfp][0], bfr[2*nfp][1],
                        bfr[2*nfp+1][0], bfr[2*nfp+1][1],
                        bs_base + boff + nfp*16*36*4);
            }
#pragma unroll
            for (int nf = 0; nf < 8; nf++)
#pragma unroll
                for (int mf = 0; mf < 2; mf++)
                    MMA_TF32(acc[mf][nf], afr[mf], bfr[nf]);
        }
        __syncthreads();
    }

#pragma unroll
    for (int mf = 0; mf < 2; mf++) {
#pragma unroll
        for (int nf = 0; nf < 8; nf++) {
            int r  = m0 + wm + mf*16 + g;
            int cb = n0 + wn + nf*8 + 2*tg;
            float2 v0 = make_float2(acc[mf][nf][0], acc[mf][nf][1]);
            float2 v1 = make_float2(acc[mf][nf][2], acc[mf][nf][3]);
            if (DOBIAS) {
                float2 bsv = *(const float2*)&bias[cb];
                v0.x += bsv.x; v0.y += bsv.y;
                v1.x += bsv.x; v1.y += bsv.y;
            }
            if (DORELU) {
                v0.x = fmaxf(v0.x, 0.f); v0.y = fmaxf(v0.y, 0.f);
                v1.x = fmaxf(v1.x, 0.f); v1.y = fmaxf(v1.y, 0.f);
            }
            if (DORES) {
                float2 r0 = *(const float2*)&res[(size_t)r*N + cb];
                float2 r1 = *(const float2*)&res[(size_t)(r+8)*N + cb];
                v0.x += r0.x; v0.y += r0.y;
                v1.x += r1.x; v1.y += r1.y;
            }
            if (DOROUND) {
                v0.x = to_tf32(v0.x); v0.y = to_tf32(v0.y);
                v1.x = to_tf32(v1.x); v1.y = to_tf32(v1.y);
            }
            *(float2*)&Cm[(size_t)r*N + cb]     = v0;
            *(float2*)&Cm[(size_t)(r+8)*N + cb] = v1;
        }
    }
}

// ---------------------------------------------------------------------------
// bf16 tensor-core flash attention (verified R6)
// ---------------------------------------------------------------------------
#define QS32 36
#define KS32 36
#define VS32 36
#define SM32_QS 0
#define SM32_KS (128*QS32)
#define SM32_VT (SM32_KS + 64*KS32)
#define ATTN_SMEM ((SM32_VT + 64*VS32)*4)
#define QSCALE 0.18033688f

#define MMA_BF16(d, a, b)                                                     \
    asm volatile(                                                             \
        "mma.sync.aligned.m16n8k16.row.col.f32.bf16.bf16.f32 "                \
        "{%0,%1,%2,%3},{%4,%5,%6,%7},{%8,%9},{%0,%1,%2,%3};\n"                \
        : "+f"((d)[0]), "+f"((d)[1]), "+f"((d)[2]), "+f"((d)[3])              \
        : "r"((a)[0]), "r"((a)[1]), "r"((a)[2]), "r"((a)[3]),                 \
          "r"((b)[0]), "r"((b)[1]))

__global__ void __launch_bounds__(256, 2) attn_tc_kernel() {
    extern __shared__ uint32_t smu[];
    uint32_t* Qs = smu + SM32_QS;
    uint32_t* Ks = smu + SM32_KS;
    uint32_t* Vt = smu + SM32_VT;

    int tid = threadIdx.x, lane = tid & 31, wid = tid >> 5;
    int g = lane >> 2, tg = lane & 3;
    int b = blockIdx.z, h = blockIdx.y;
    int tq0 = blockIdx.x * 128;
    int wr = wid * 16;

    const float* qbase = g_qkv + (size_t)b*TT*3*CC + (size_t)h*HS;
    const float* kbase = qbase + CC;
    const float* vbase = qbase + 2*CC;

#pragma unroll
    for (int p = 0; p < 8; p++) {
        int idx = tid + p*256;
        int r = idx >> 4, c4 = idx & 15;
        float4 v = *(const float4*)&qbase[(size_t)(tq0 + r)*3*CC + c4*4];
        Qs[r*QS32 + c4*2    ] = pack_bf16x2(v.x*QSCALE, v.y*QSCALE);
        Qs[r*QS32 + c4*2 + 1] = pack_bf16x2(v.z*QSCALE, v.w*QSCALE);
    }

    float o[8][4];
#pragma unroll
    for (int i = 0; i < 8; i++)
#pragma unroll
        for (int j = 0; j < 4; j++) o[i][j] = 0.f;
    float lsum0 = 0.f, lsum1 = 0.f;

    __syncthreads();

    for (int kt = 0; kt < TT; kt += 64) {
#pragma unroll
        for (int p = 0; p < 4; p++) {
            int idx = tid + p*256;
            int r = idx >> 4, c4 = idx & 15;
            float4 v = *(const float4*)&kbase[(size_t)(kt + r)*3*CC + c4*4];
            Ks[r*KS32 + c4*2    ] = pack_bf16x2(v.x, v.y);
            Ks[r*KS32 + c4*2 + 1] = pack_bf16x2(v.z, v.w);
        }
#pragma unroll
        for (int p = 0; p < 2; p++) {
            int idx = tid + p*256;
            int sp = idx & 31, dg = idx >> 5;
            int d0 = dg * 4;
            float4 v0 = *(const float4*)&vbase[(size_t)(kt + 2*sp    )*3*CC + d0];
            float4 v1 = *(const float4*)&vbase[(size_t)(kt + 2*sp + 1)*3*CC + d0];
            Vt[(d0    )*VS32 + sp] = pack_bf16x2(v0.x, v1.x);
            Vt[(d0 + 1)*VS32 + sp] = pack_bf16x2(v0.y, v1.y);
            Vt[(d0 + 2)*VS32 + sp] = pack_bf16x2(v0.z, v1.z);
            Vt[(d0 + 3)*VS32 + sp] = pack_bf16x2(v0.w, v1.w);
        }
        __syncthreads();

        float s[8][4];
#pragma unroll
        for (int nf = 0; nf < 8; nf++)
#pragma unroll
            for (int j = 0; j < 4; j++) s[nf][j] = 0.f;

#pragma unroll
        for (int c = 0; c < 4; c++) {
            int c8 = c * 8;
            uint32_t aq[4];
            aq[0] = Qs[(wr+g  )*QS32 + c8 + tg    ];
            aq[1] = Qs[(wr+g+8)*QS32 + c8 + tg    ];
            aq[2] = Qs[(wr+g  )*QS32 + c8 + tg + 4];
            aq[3] = Qs[(wr+g+8)*QS32 + c8 + tg + 4];
#pragma unroll
            for (int nf = 0; nf < 8; nf++) {
                uint32_t bk[2];
                bk[0] = Ks[(nf*8+g)*KS32 + c8 + tg    ];
                bk[1] = Ks[(nf*8+g)*KS32 + c8 + tg + 4];
                MMA_BF16(s[nf], aq, bk);
            }
        }

#pragma unroll
        for (int nf = 0; nf < 8; nf++) {
            if (nf < 4) {
                s[nf][0] = ex2_mufu(fminf(s[nf][0], 80.f));
                s[nf][1] = ex2_mufu(fminf(s[nf][1], 80.f));
                s[nf][2] = ex2_mufu(fminf(s[nf][2], 80.f));
                s[nf][3] = ex2_mufu(fminf(s[nf][3], 80.f));
            } else {
                s[nf][0] = ex2_poly(fminf(fmaxf(s[nf][0], -80.f), 80.f));
                s[nf][1] = ex2_poly(fminf(fmaxf(s[nf][1], -80.f), 80.f));
                s[nf][2] = ex2_poly(fminf(fmaxf(s[nf][2], -80.f), 80.f));
                s[nf][3] = ex2_poly(fminf(fmaxf(s[nf][3], -80.f), 80.f));
            }
            lsum0 += s[nf][0] + s[nf][1];
            lsum1 += s[nf][2] + s[nf][3];
        }

#pragma unroll
        for (int j = 0; j < 4; j++) {
            uint32_t ap[4];
            ap[0] = pack_bf16x2(s[2*j  ][0], s[2*j  ][1]);
            ap[1] = pack_bf16x2(s[2*j  ][2], s[2*j  ][3]);
            ap[2] = pack_bf16x2(s[2*j+1][0], s[2*j+1][1]);
            ap[3] = pack_bf16x2(s[2*j+1][2], s[2*j+1][3]);
            int c8 = j * 8;
#pragma unroll
            for (int nf = 0; nf < 8; nf++) {
                uint32_t bv[2];
                bv[0] = Vt[(nf*8+g)*VS32 + c8 + tg    ];
                bv[1] = Vt[(nf*8+g)*VS32 + c8 + tg + 4];
                MMA_BF16(o[nf], ap, bv);
            }
        }
        __syncthreads();
    }

    lsum0 += __shfl_xor_sync(0xffffffffu, lsum0, 1);
    lsum0 += __shfl_xor_sync(0xffffffffu, lsum0, 2);
    lsum1 += __shfl_xor_sync(0xffffffffu, lsum1, 1);
    lsum1 += __shfl_xor_sync(0xffffffffu, lsum1, 2);
    float inv0 = 1.0f / lsum0, inv1 = 1.0f / lsum1;

    int row0 = b*TT + tq0 + wr + g;
#pragma unroll
    for (int nf = 0; nf < 8; nf++) {
        int col = h*HS + nf*8 + 2*tg;
        float2 v0 = make_float2(to_tf32(o[nf][0]*inv0), to_tf32(o[nf][1]*inv0));
        float2 v1 = make_float2(to_tf32(o[nf][2]*inv1), to_tf32(o[nf][3]*inv1));
        *(float2*)&g_attn[(size_t)row0*CC + col]     = v0;
        *(float2*)&g_attn[(size_t)(row0+8)*CC + col] = v1;
    }
}

// ---------------------------------------------------------------------------
// Launch
// ---------------------------------------------------------------------------
extern "C" void kernel_launch(void* const* d_in, const int* in_sizes, int n_in,
                              void* d_out, int out_size) {
    const float* x      = (const float*)d_in[0];
    const float* Wq     = (const float*)d_in[1];
    const float* bq     = (const float*)d_in[2];
    const float* Wk     = (const float*)d_in[3];
    const float* bk     = (const float*)d_in[4];
    const float* Wv     = (const float*)d_in[5];
    const float* bv     = (const float*)d_in[6];
    const float* Wo     = (const float*)d_in[7];
    const float* bo     = (const float*)d_in[8];
    const float* W1     = (const float*)d_in[9];
    const float* b1     = (const float*)d_in[10];
    const float* W2     = (const float*)d_in[11];
    const float* b2     = (const float*)d_in[12];
    const float* gamma1 = (const float*)d_in[13];
    const float* beta1  = (const float*)d_in[14];
    const float* gamma2 = (const float*)d_in[15];
    const float* beta2  = (const float*)d_in[16];
    float* out = (float*)d_out;

    float *p_h, *p_wqkv, *p_bqkv, *p_qkv, *p_attn, *p_x1, *p_h2, *p_ff;
    float *p_wor, *p_w1r, *p_w2r;
    cudaGetSymbolAddress((void**)&p_h,    g_h);
    cudaGetSymbolAddress((void**)&p_wqkv, g_wqkv);
    cudaGetSymbolAddress((void**)&p_bqkv, g_bqkv);
    cudaGetSymbolAddress((void**)&p_qkv,  g_qkv);
    cudaGetSymbolAddress((void**)&p_attn, g_attn);
    cudaGetSymbolAddress((void**)&p_x1,   g_x1);
    cudaGetSymbolAddress((void**)&p_h2,   g_h2);
    cudaGetSymbolAddress((void**)&p_ff,   g_ff);
    cudaGetSymbolAddress((void**)&p_wor,  g_wor);
    cudaGetSymbolAddress((void**)&p_w1r,  g_w1r);
    cudaGetSymbolAddress((void**)&p_w2r,  g_w2r);

    cudaFuncSetAttribute(attn_tc_kernel,
                         cudaFuncAttributeMaxDynamicSharedMemorySize, ATTN_SMEM);
    cudaFuncSetAttribute(gemm_tc_kernel<1,0,0,0>,
                         cudaFuncAttributeMaxDynamicSharedMemorySize, GEMM_SMEM);
    cudaFuncSetAttribute(gemm_tc_kernel<1,0,1,0>,
                         cudaFuncAttributeMaxDynamicSharedMemorySize, GEMM_SMEM);
    cudaFuncSetAttribute(gemm_tc_kernel<1,1,0,1>,
                         cudaFuncAttributeMaxDynamicSharedMemorySize, GEMM_SMEM);

    // 0. weight permutes (chunked n-major layout, tf32-rounded)
    pack_qkv_perm_kernel<<<dim3(CC/32, HH), 256>>>(Wq, Wk, Wv);
    pack_bias_kernel<<<(CC + 255)/256, 256>>>(bq, bk, bv);
    permute_w_kernel<<<dim3(CC/64,   CC/32),  256>>>(Wo, p_wor, CC,   CC);
    permute_w_kernel<<<dim3(4*CC/64, CC/32),  256>>>(W1, p_w1r, CC,   4*CC);
    permute_w_kernel<<<dim3(CC/64,   4*CC/32),256>>>(W2, p_w2r, 4*CC, CC);

    // 1. LN1
    ln_seq_kernel<<<dim3(CC/32, BB), dim3(32, 32)>>>(x, gamma1, beta1, p_h);

    // 2. QKV GEMM: [4096,1024] @ [1024,3072]
    gemm_tc_kernel<1,0,0,0><<<dim3(3*CC/128, NROWS/128), 256, GEMM_SMEM>>>(
        p_h, p_wqkv, p_bqkv, nullptr, p_qkv, NROWS, 3*CC, CC);

    // 3. attention
    attn_tc_kernel<<<dim3(TT/128, HH, BB), 256, ATTN_SMEM>>>();

    // 4. output projection + residual
    gemm_tc_kernel<1,0,1,0><<<dim3(CC/128, NROWS/128), 256, GEMM_SMEM>>>(
        p_attn, p_wor, bo, x, p_x1, NROWS, CC, CC);

    // 5. LN2
    ln_seq_kernel<<<dim3(CC/32, BB), dim3(32, 32)>>>(p_x1, gamma2, beta2, p_h2);

    // 6. FF1 + relu (rounded output)
    gemm_tc_kernel<1,1,0,1><<<dim3(4*CC/128, NROWS/128), 256, GEMM_SMEM>>>(
        p_h2, p_w1r, b1, nullptr, p_ff, NROWS, 4*CC, CC);

    // 7. FF2 + residual -> out
    gemm_tc_kernel<1,0,1,0><<<dim3(CC/128, NROWS/128), 256, GEMM_SMEM>>>(
        p_ff, p_w2r, b2, p_x1, out, NROWS, CC, 4*CC);
}